// round 4
// baseline (speedup 1.0000x reference)
#include <cuda_runtime.h>
#include <math.h>

#define EPSF 1e-5f

__device__ __forceinline__ float4 f4_fma(float a, float4 w, float4 acc) {
    acc.x = fmaf(a, w.x, acc.x);
    acc.y = fmaf(a, w.y, acc.y);
    acc.z = fmaf(a, w.z, acc.z);
    acc.w = fmaf(a, w.w, acc.w);
    return acc;
}
__device__ __forceinline__ float4 f4_mul(float a, float4 w) {
    return make_float4(a * w.x, a * w.y, a * w.z, a * w.w);
}
__device__ __forceinline__ float4 f4_add(float4 a, float4 b) {
    return make_float4(a.x + b.x, a.y + b.y, a.z + b.z, a.w + b.w);
}
__device__ __forceinline__ float f4_dot(float4 a, float4 b) {
    return a.x * b.x + a.y * b.y + a.z * b.z + a.w * b.w;
}

// SMEM layout (floats):
//  Xs   [288*16]      = 4608   @0
//  rS   [288*32]      = 9216   @4608
//  vbuf [8*32*16]     = 4096   @13824
//  vcur [32*16]       = 512    @17920
//  invd [32]          = 32     @18432
//  mred [8*32]        = 256    @18464
//  nred [8*32]        = 256    @18720
//  total 18976 floats = 75904 bytes
#define SMEM_FLOATS 18976

// p_out has 4*32*16*8*8 = 131072 elements; a_out follows it.
#define AOUT_BASE 131072

// Compute u_raw[16] = X[B] (4x4) @ W[B,C] (4x4) for C = lane.
#define COMPUTE_U(B)                                                           \
    const float4* Wp = Wv + ((((B) << 5) + lane) << 2);                        \
    float4 w0 = Wp[0], w1 = Wp[1], w2 = Wp[2], w3 = Wp[3];                     \
    const float4* Xp = Xv + ((B) << 2);                                        \
    float4 xr0 = Xp[0], xr1 = Xp[1], xr2 = Xp[2], xr3 = Xp[3];                 \
    float4 u0 = f4_mul(xr0.x, w0);                                             \
    u0 = f4_fma(xr0.y, w1, u0); u0 = f4_fma(xr0.z, w2, u0); u0 = f4_fma(xr0.w, w3, u0); \
    float4 u1 = f4_mul(xr1.x, w0);                                             \
    u1 = f4_fma(xr1.y, w1, u1); u1 = f4_fma(xr1.z, w2, u1); u1 = f4_fma(xr1.w, w3, u1); \
    float4 u2 = f4_mul(xr2.x, w0);                                             \
    u2 = f4_fma(xr2.y, w1, u2); u2 = f4_fma(xr2.z, w2, u2); u2 = f4_fma(xr2.w, w3, u2); \
    float4 u3 = f4_mul(xr3.x, w0);                                             \
    u3 = f4_fma(xr3.y, w1, u3); u3 = f4_fma(xr3.z, w2, u3); u3 = f4_fma(xr3.w, w3, u3);

__global__ __launch_bounds__(256, 2)
void convcaps_kernel(const float* __restrict__ x,
                     const float* __restrict__ Wg,
                     float* __restrict__ out) {
    extern __shared__ float smem[];
    float* Xs   = smem;
    float* rS   = smem + 4608;
    float* vbuf = smem + 13824;
    float* vcur = smem + 17920;
    float* invd = smem + 18432;
    float* mred = smem + 18464;
    float* nred = smem + 18720;

    const int tid  = threadIdx.x;
    const int lane = tid & 31;     // = C for the voting loops
    const int wp   = tid >> 5;     // warp id, B ≡ wp (mod 8)
    const int pos  = blockIdx.x;   // b*64 + h*8 + w
    const int b    = pos >> 6;
    const int hw   = pos & 63;
    const int h    = hw >> 3;
    const int w    = hw & 7;

    // ---- gather patch poses X[B_=B*9+ki*3+kj][ps] with zero padding ----
    for (int idx = tid; idx < 4608; idx += 256) {
        int B_ = idx >> 4, p = idx & 15;
        int Bcap = B_ / 9;
        int kk = B_ - Bcap * 9;
        int ki = kk / 3, kj = kk - ki * 3;
        int hh = 2 * h + ki - 1, ww = 2 * w + kj - 1;
        float val = 0.f;
        if ((unsigned)hh < 16u && (unsigned)ww < 16u)
            val = x[(((b * 32 + Bcap) * 16 + p) << 8) + (hh << 4) + ww];
        Xs[idx] = val;
    }
    __syncthreads();

    const float4* Wv    = reinterpret_cast<const float4*>(Wg);
    const float4* Xv    = reinterpret_cast<const float4*>(Xs);
    float4*       vbufv = reinterpret_cast<float4*>(vbuf);
    float4*       vcurv = reinterpret_cast<float4*>(vcur);

    // ================= PASS A: norms (for max-min) + uniform sum ==========
    float4 a0 = make_float4(0, 0, 0, 0), a1 = a0, a2 = a0, a3 = a0;
    float mx = -3.4e38f, mn = 3.4e38f;
    for (int B = wp; B < 288; B += 8) {
        COMPUTE_U(B)
        float ss = f4_dot(u0, u0) + f4_dot(u1, u1) + f4_dot(u2, u2) + f4_dot(u3, u3);
        float nrm = sqrtf(ss + EPSF);
        mx = fmaxf(mx, nrm);
        mn = fminf(mn, nrm);
        a0 = f4_add(a0, u0); a1 = f4_add(a1, u1);
        a2 = f4_add(a2, u2); a3 = f4_add(a3, u3);
    }
    mred[(wp << 5) + lane] = mx;
    nred[(wp << 5) + lane] = mn;
    {
        int base = ((wp << 5) + lane) << 2;
        vbufv[base + 0] = a0; vbufv[base + 1] = a1;
        vbufv[base + 2] = a2; vbufv[base + 3] = a3;
    }
    __syncthreads();
    if (tid < 32) {
        float M = -3.4e38f, m = 3.4e38f;
        #pragma unroll
        for (int k = 0; k < 8; k++) {
            M = fmaxf(M, mred[(k << 5) + tid]);
            m = fminf(m, nred[(k << 5) + tid]);
        }
        invd[tid] = 1.f / (M - m);
    }
    __syncthreads();
    // reduce across warps + squash -> v0
    if (tid < 128) {
        int C = tid >> 2;
        float4 acc = vbufv[tid];
        #pragma unroll
        for (int k = 1; k < 8; k++) acc = f4_add(acc, vbufv[(k << 7) + tid]);
        float f = invd[C] * (1.f / 32.f);   // uniform c = 1/32, u = u_raw/d
        acc = f4_mul(f, acc);
        float s = f4_dot(acc, acc);
        s += __shfl_xor_sync(0xffffffffu, s, 1);
        s += __shfl_xor_sync(0xffffffffu, s, 2);
        float nrm = sqrtf(s + EPSF);
        vcurv[tid] = f4_mul(1.f / (1.f + nrm), acc);
    }
    __syncthreads();

    const float invd_c = invd[lane];

    // ================= PASS B: r1 = u.v0, c1 = softmax_C, accum c1*u ======
    {
        float4 vl0 = vcurv[(lane << 2) + 0], vl1 = vcurv[(lane << 2) + 1];
        float4 vl2 = vcurv[(lane << 2) + 2], vl3 = vcurv[(lane << 2) + 3];
        a0 = make_float4(0, 0, 0, 0); a1 = a0; a2 = a0; a3 = a0;
        for (int B = wp; B < 288; B += 8) {
            COMPUTE_U(B)
            float dt = f4_dot(u0, vl0) + f4_dot(u1, vl1) +
                       f4_dot(u2, vl2) + f4_dot(u3, vl3);
            float rB = dt * invd_c;
            rS[(B << 5) + lane] = rB;
            float m = rB;
            #pragma unroll
            for (int o = 16; o > 0; o >>= 1)
                m = fmaxf(m, __shfl_xor_sync(0xffffffffu, m, o));
            float e = __expf(rB - m);
            float se = e;
            #pragma unroll
            for (int o = 16; o > 0; o >>= 1)
                se += __shfl_xor_sync(0xffffffffu, se, o);
            float c = e / se;
            a0 = f4_fma(c, u0, a0); a1 = f4_fma(c, u1, a1);
            a2 = f4_fma(c, u2, a2); a3 = f4_fma(c, u3, a3);
        }
        int base = ((wp << 5) + lane) << 2;
        vbufv[base + 0] = a0; vbufv[base + 1] = a1;
        vbufv[base + 2] = a2; vbufv[base + 3] = a3;
    }
    __syncthreads();
    if (tid < 128) {
        int C = tid >> 2;
        float4 acc = vbufv[tid];
        #pragma unroll
        for (int k = 1; k < 8; k++) acc = f4_add(acc, vbufv[(k << 7) + tid]);
        acc = f4_mul(invd[C], acc);
        float s = f4_dot(acc, acc);
        s += __shfl_xor_sync(0xffffffffu, s, 1);
        s += __shfl_xor_sync(0xffffffffu, s, 2);
        float nrm = sqrtf(s + EPSF);
        vcurv[tid] = f4_mul(1.f / (1.f + nrm), acc);
    }
    __syncthreads();

    // ================= PASS C: r2 = r1 + u.v1, c2, accum, output ==========
    {
        float4 vl0 = vcurv[(lane << 2) + 0], vl1 = vcurv[(lane << 2) + 1];
        float4 vl2 = vcurv[(lane << 2) + 2], vl3 = vcurv[(lane << 2) + 3];
        a0 = make_float4(0, 0, 0, 0); a1 = a0; a2 = a0; a3 = a0;
        for (int B = wp; B < 288; B += 8) {
            COMPUTE_U(B)
            float dt = f4_dot(u0, vl0) + f4_dot(u1, vl1) +
                       f4_dot(u2, vl2) + f4_dot(u3, vl3);
            float rB = rS[(B << 5) + lane] + dt * invd_c;
            float m = rB;
            #pragma unroll
            for (int o = 16; o > 0; o >>= 1)
                m = fmaxf(m, __shfl_xor_sync(0xffffffffu, m, o));
            float e = __expf(rB - m);
            float se = e;
            #pragma unroll
            for (int o = 16; o > 0; o >>= 1)
                se += __shfl_xor_sync(0xffffffffu, se, o);
            float c = e / se;
            a0 = f4_fma(c, u0, a0); a1 = f4_fma(c, u1, a1);
            a2 = f4_fma(c, u2, a2); a3 = f4_fma(c, u3, a3);
        }
        int base = ((wp << 5) + lane) << 2;
        vbufv[base + 0] = a0; vbufv[base + 1] = a1;
        vbufv[base + 2] = a2; vbufv[base + 3] = a3;
    }
    __syncthreads();
    if (tid < 128) {
        int C = tid >> 2, q = tid & 3;
        float4 acc = vbufv[tid];
        #pragma unroll
        for (int k = 1; k < 8; k++) acc = f4_add(acc, vbufv[(k << 7) + tid]);
        acc = f4_mul(invd[C], acc);
        float s = f4_dot(acc, acc);
        s += __shfl_xor_sync(0xffffffffu, s, 1);
        s += __shfl_xor_sync(0xffffffffu, s, 2);
        float nrm = sqrtf(s + EPSF);
        acc = f4_mul(1.f / (1.f + nrm), acc);        // v2 (p_out)
        float s2 = f4_dot(acc, acc);
        s2 += __shfl_xor_sync(0xffffffffu, s2, 1);
        s2 += __shfl_xor_sync(0xffffffffu, s2, 2);
        float aout = sqrtf(s2 + EPSF);               // a_out = safe_norm(v2)
        // p_out[b, C, ps, h, w]; ps = q*4 .. q*4+3
        int basep = (((b * 32 + C) * 16 + (q << 2)) << 6) + hw;
        out[basep]       = acc.x;
        out[basep + 64]  = acc.y;
        out[basep + 128] = acc.z;
        out[basep + 192] = acc.w;
        if (q == 0)
            out[AOUT_BASE + ((b * 32 + C) << 6) + hw] = aout;
    }
}

extern "C" void kernel_launch(void* const* d_in, const int* in_sizes, int n_in,
                              void* d_out, int out_size) {
    (void)out_size;
    // Resolve inputs BY SIZE — immune to metadata ordering.
    //   x:    4*32*16*16*16 = 524288
    //   a:    4*32*16*16    =  32768 (unused by the reference computation)
    //   W_ij: 288*32*4*4    = 147456
    const float* x  = nullptr;
    const float* Wg = nullptr;
    for (int i = 0; i < n_in; i++) {
        if (in_sizes[i] == 524288)      x  = (const float*)d_in[i];
        else if (in_sizes[i] == 147456) Wg = (const float*)d_in[i];
    }
    float* out = (float*)d_out;

    const size_t smem_bytes = SMEM_FLOATS * sizeof(float);
    cudaFuncSetAttribute(convcaps_kernel,
                         cudaFuncAttributeMaxDynamicSharedMemorySize,
                         (int)smem_bytes);
    convcaps_kernel<<<256, 256, smem_bytes>>>(x, Wg, out);
}

// round 5
// speedup vs baseline: 1.2444x; 1.2444x over previous
#include <cuda_runtime.h>
#include <math.h>

#define EPSF 1e-5f

// Transposed weights: Wt[B][jk][C], B<288, jk<16, C<32.
__device__ float Wt_buf[288 * 16 * 32];

__global__ void transpose_W_kernel(const float* __restrict__ Wg) {
    int idx = blockIdx.x * 256 + threadIdx.x;   // output-linear: (B*16+jk)*32 + C
    if (idx >= 288 * 16 * 32) return;
    int C  = idx & 31;
    int t  = idx >> 5;          // B*16 + jk
    int jk = t & 15;
    int B  = t >> 4;
    Wt_buf[idx] = Wg[((B << 5) + C) * 16 + jk];
}

__device__ __forceinline__ float4 f4_fma(float a, float4 w, float4 acc) {
    acc.x = fmaf(a, w.x, acc.x);
    acc.y = fmaf(a, w.y, acc.y);
    acc.z = fmaf(a, w.z, acc.z);
    acc.w = fmaf(a, w.w, acc.w);
    return acc;
}
__device__ __forceinline__ float4 f4_mul(float a, float4 w) {
    return make_float4(a * w.x, a * w.y, a * w.z, a * w.w);
}
__device__ __forceinline__ float4 f4_add(float4 a, float4 b) {
    return make_float4(a.x + b.x, a.y + b.y, a.z + b.z, a.w + b.w);
}
__device__ __forceinline__ float f4_dot(float4 a, float4 b) {
    return a.x * b.x + a.y * b.y + a.z * b.z + a.w * b.w;
}

// SMEM layout (floats):
//  Xs   [288*16]      = 4608   @0
//  rS   [288*32]      = 9216   @4608
//  vbuf [8*32*16]     = 4096   @13824
//  vcur [32*16]       = 512    @17920
//  invd [32]          = 32     @18432
//  mred [8*32]        = 256    @18464
//  nred [8*32]        = 256    @18720
#define SMEM_FLOATS 18976

// p_out has 4*32*16*8*8 = 131072 elements; a_out follows it.
#define AOUT_BASE 131072

// u_raw[16] = X[B] (4x4) @ W[B,C] (4x4), C = lane. Coalesced W loads (stride 128B).
#define COMPUTE_U(B)                                                           \
    const float* Wp = Wt_buf + ((B) << 9) + lane;                              \
    float4 w0, w1, w2, w3;                                                     \
    w0.x = Wp[0];   w0.y = Wp[32];  w0.z = Wp[64];  w0.w = Wp[96];             \
    w1.x = Wp[128]; w1.y = Wp[160]; w1.z = Wp[192]; w1.w = Wp[224];            \
    w2.x = Wp[256]; w2.y = Wp[288]; w2.z = Wp[320]; w2.w = Wp[352];            \
    w3.x = Wp[384]; w3.y = Wp[416]; w3.z = Wp[448]; w3.w = Wp[480];            \
    const float4* Xp = Xv + ((B) << 2);                                        \
    float4 xr0 = Xp[0], xr1 = Xp[1], xr2 = Xp[2], xr3 = Xp[3];                 \
    float4 u0 = f4_mul(xr0.x, w0);                                             \
    u0 = f4_fma(xr0.y, w1, u0); u0 = f4_fma(xr0.z, w2, u0); u0 = f4_fma(xr0.w, w3, u0); \
    float4 u1 = f4_mul(xr1.x, w0);                                             \
    u1 = f4_fma(xr1.y, w1, u1); u1 = f4_fma(xr1.z, w2, u1); u1 = f4_fma(xr1.w, w3, u1); \
    float4 u2 = f4_mul(xr2.x, w0);                                             \
    u2 = f4_fma(xr2.y, w1, u2); u2 = f4_fma(xr2.z, w2, u2); u2 = f4_fma(xr2.w, w3, u2); \
    float4 u3 = f4_mul(xr3.x, w0);                                             \
    u3 = f4_fma(xr3.y, w1, u3); u3 = f4_fma(xr3.z, w2, u3); u3 = f4_fma(xr3.w, w3, u3);

__global__ __launch_bounds__(256, 2)
void convcaps_kernel(const float* __restrict__ x,
                     float* __restrict__ out) {
    extern __shared__ float smem[];
    float* Xs   = smem;
    float* rS   = smem + 4608;
    float* vbuf = smem + 13824;
    float* vcur = smem + 17920;
    float* invd = smem + 18432;
    float* mred = smem + 18464;
    float* nred = smem + 18720;

    const int tid  = threadIdx.x;
    const int lane = tid & 31;     // = C
    const int wp   = tid >> 5;     // warp id, B ≡ wp (mod 8)
    const int pos  = blockIdx.x;   // b*64 + h*8 + w
    const int b    = pos >> 6;
    const int hw   = pos & 63;
    const int h    = hw >> 3;
    const int w    = hw & 7;

    // ---- gather patch poses X[B_=Bcap*9+ki*3+kj][ps] with zero padding ----
    for (int idx = tid; idx < 4608; idx += 256) {
        int B_ = idx >> 4, p = idx & 15;
        int Bcap = B_ / 9;
        int kk = B_ - Bcap * 9;
        int ki = kk / 3, kj = kk - ki * 3;
        int hh = 2 * h + ki - 1, ww = 2 * w + kj - 1;
        float val = 0.f;
        if ((unsigned)hh < 16u && (unsigned)ww < 16u)
            val = x[(((b * 32 + Bcap) * 16 + p) << 8) + (hh << 4) + ww];
        Xs[idx] = val;
    }
    __syncthreads();

    const float4* Xv    = reinterpret_cast<const float4*>(Xs);
    float4*       vbufv = reinterpret_cast<float4*>(vbuf);
    float4*       vcurv = reinterpret_cast<float4*>(vcur);

    // ================= PASS A: norms (for max-min) + uniform sum ==========
    float4 a0 = make_float4(0, 0, 0, 0), a1 = a0, a2 = a0, a3 = a0;
    float mx = -3.4e38f, mn = 3.4e38f;
    for (int B = wp; B < 288; B += 8) {
        COMPUTE_U(B)
        float ss = f4_dot(u0, u0) + f4_dot(u1, u1) + f4_dot(u2, u2) + f4_dot(u3, u3);
        float nrm = sqrtf(ss + EPSF);
        mx = fmaxf(mx, nrm);
        mn = fminf(mn, nrm);
        a0 = f4_add(a0, u0); a1 = f4_add(a1, u1);
        a2 = f4_add(a2, u2); a3 = f4_add(a3, u3);
    }
    mred[(wp << 5) + lane] = mx;
    nred[(wp << 5) + lane] = mn;
    {
        int base = ((wp << 5) + lane) << 2;
        vbufv[base + 0] = a0; vbufv[base + 1] = a1;
        vbufv[base + 2] = a2; vbufv[base + 3] = a3;
    }
    __syncthreads();
    if (tid < 32) {
        float M = -3.4e38f, m = 3.4e38f;
        #pragma unroll
        for (int k = 0; k < 8; k++) {
            M = fmaxf(M, mred[(k << 5) + tid]);
            m = fminf(m, nred[(k << 5) + tid]);
        }
        invd[tid] = 1.f / (M - m);
    }
    __syncthreads();
    // reduce across warps + squash -> v0
    if (tid < 128) {
        int C = tid >> 2;
        float4 acc = vbufv[tid];
        #pragma unroll
        for (int k = 1; k < 8; k++) acc = f4_add(acc, vbufv[(k << 7) + tid]);
        float f = invd[C] * (1.f / 32.f);   // uniform c = 1/32, u = u_raw/d
        acc = f4_mul(f, acc);
        float s = f4_dot(acc, acc);
        s += __shfl_xor_sync(0xffffffffu, s, 1);
        s += __shfl_xor_sync(0xffffffffu, s, 2);
        float nrm = sqrtf(s + EPSF);
        vcurv[tid] = f4_mul(1.f / (1.f + nrm), acc);
    }
    __syncthreads();

    const float invd_c = invd[lane];

    // ================= PASS B: r1 = u.v0, c1 = softmax_C, accum c1*u ======
    {
        float4 vl0 = vcurv[(lane << 2) + 0], vl1 = vcurv[(lane << 2) + 1];
        float4 vl2 = vcurv[(lane << 2) + 2], vl3 = vcurv[(lane << 2) + 3];
        a0 = make_float4(0, 0, 0, 0); a1 = a0; a2 = a0; a3 = a0;
        for (int B = wp; B < 288; B += 8) {
            COMPUTE_U(B)
            float dt = f4_dot(u0, vl0) + f4_dot(u1, vl1) +
                       f4_dot(u2, vl2) + f4_dot(u3, vl3);
            float rB = dt * invd_c;
            rS[(B << 5) + lane] = rB;
            float e = __expf(rB);           // softmax over C, max-shift dropped (|r| small)
            float se = e;
            #pragma unroll
            for (int o = 16; o > 0; o >>= 1)
                se += __shfl_xor_sync(0xffffffffu, se, o);
            float c = e / se;
            a0 = f4_fma(c, u0, a0); a1 = f4_fma(c, u1, a1);
            a2 = f4_fma(c, u2, a2); a3 = f4_fma(c, u3, a3);
        }
        int base = ((wp << 5) + lane) << 2;
        vbufv[base + 0] = a0; vbufv[base + 1] = a1;
        vbufv[base + 2] = a2; vbufv[base + 3] = a3;
    }
    __syncthreads();
    if (tid < 128) {
        int C = tid >> 2;
        float4 acc = vbufv[tid];
        #pragma unroll
        for (int k = 1; k < 8; k++) acc = f4_add(acc, vbufv[(k << 7) + tid]);
        acc = f4_mul(invd[C], acc);
        float s = f4_dot(acc, acc);
        s += __shfl_xor_sync(0xffffffffu, s, 1);
        s += __shfl_xor_sync(0xffffffffu, s, 2);
        float nrm = sqrtf(s + EPSF);
        vcurv[tid] = f4_mul(1.f / (1.f + nrm), acc);
    }
    __syncthreads();

    // ================= PASS C: r2 = r1 + u.v1, c2, accum, output ==========
    {
        float4 vl0 = vcurv[(lane << 2) + 0], vl1 = vcurv[(lane << 2) + 1];
        float4 vl2 = vcurv[(lane << 2) + 2], vl3 = vcurv[(lane << 2) + 3];
        a0 = make_float4(0, 0, 0, 0); a1 = a0; a2 = a0; a3 = a0;
        for (int B = wp; B < 288; B += 8) {
            COMPUTE_U(B)
            float dt = f4_dot(u0, vl0) + f4_dot(u1, vl1) +
                       f4_dot(u2, vl2) + f4_dot(u3, vl3);
            float rB = rS[(B << 5) + lane] + dt * invd_c;
            float e = __expf(rB);
            float se = e;
            #pragma unroll
            for (int o = 16; o > 0; o >>= 1)
                se += __shfl_xor_sync(0xffffffffu, se, o);
            float c = e / se;
            a0 = f4_fma(c, u0, a0); a1 = f4_fma(c, u1, a1);
            a2 = f4_fma(c, u2, a2); a3 = f4_fma(c, u3, a3);
        }
        int base = ((wp << 5) + lane) << 2;
        vbufv[base + 0] = a0; vbufv[base + 1] = a1;
        vbufv[base + 2] = a2; vbufv[base + 3] = a3;
    }
    __syncthreads();
    if (tid < 128) {
        int C = tid >> 2, q = tid & 3;
        float4 acc = vbufv[tid];
        #pragma unroll
        for (int k = 1; k < 8; k++) acc = f4_add(acc, vbufv[(k << 7) + tid]);
        acc = f4_mul(invd[C], acc);
        float s = f4_dot(acc, acc);
        s += __shfl_xor_sync(0xffffffffu, s, 1);
        s += __shfl_xor_sync(0xffffffffu, s, 2);
        float nrm = sqrtf(s + EPSF);
        acc = f4_mul(1.f / (1.f + nrm), acc);        // v2 (p_out)
        float s2 = f4_dot(acc, acc);
        s2 += __shfl_xor_sync(0xffffffffu, s2, 1);
        s2 += __shfl_xor_sync(0xffffffffu, s2, 2);
        float aout = sqrtf(s2 + EPSF);               // a_out = safe_norm(v2)
        // p_out[b, C, ps, h, w]; ps = q*4 .. q*4+3
        int basep = (((b * 32 + C) * 16 + (q << 2)) << 6) + hw;
        out[basep]       = acc.x;
        out[basep + 64]  = acc.y;
        out[basep + 128] = acc.z;
        out[basep + 192] = acc.w;
        if (q == 0)
            out[AOUT_BASE + ((b * 32 + C) << 6) + hw] = aout;
    }
}

extern "C" void kernel_launch(void* const* d_in, const int* in_sizes, int n_in,
                              void* d_out, int out_size) {
    (void)out_size;
    // Resolve inputs BY SIZE — immune to metadata ordering.
    //   x:    4*32*16*16*16 = 524288
    //   a:    4*32*16*16    =  32768 (unused by the reference computation)
    //   W_ij: 288*32*4*4    = 147456
    const float* x  = nullptr;
    const float* Wg = nullptr;
    for (int i = 0; i < n_in; i++) {
        if (in_sizes[i] == 524288)      x  = (const float*)d_in[i];
        else if (in_sizes[i] == 147456) Wg = (const float*)d_in[i];
    }
    float* out = (float*)d_out;

    transpose_W_kernel<<<(288 * 16 * 32 + 255) / 256, 256>>>(Wg);

    const size_t smem_bytes = SMEM_FLOATS * sizeof(float);
    cudaFuncSetAttribute(convcaps_kernel,
                         cudaFuncAttributeMaxDynamicSharedMemorySize,
                         (int)smem_bytes);
    convcaps_kernel<<<256, 256, smem_bytes>>>(x, out);
}

// round 6
// speedup vs baseline: 1.4636x; 1.1762x over previous
#include <cuda_runtime.h>
#include <math.h>

#define EPSF 1e-5f

// Re-laid-out weights: Wt4[B][g][C] (float4), g = jk/4.
// Wt4[(B*4+g)*32 + C] = { W[B][C][4g], ..., W[B][C][4g+3] }
__device__ float4 Wt4_buf[288 * 4 * 32];

__global__ void transpose_W_kernel(const float* __restrict__ Wg) {
    int idx = blockIdx.x * 256 + threadIdx.x;   // linear over output floats
    if (idx >= 288 * 16 * 32) return;
    int q = idx & 3;
    int C = (idx >> 2) & 31;
    int g = (idx >> 7) & 3;
    int B = idx >> 9;
    ((float*)Wt4_buf)[idx] = Wg[((B << 5) + C) * 16 + (g << 2) + q];
}

__device__ __forceinline__ float4 f4_fma(float a, float4 w, float4 acc) {
    acc.x = fmaf(a, w.x, acc.x);
    acc.y = fmaf(a, w.y, acc.y);
    acc.z = fmaf(a, w.z, acc.z);
    acc.w = fmaf(a, w.w, acc.w);
    return acc;
}
__device__ __forceinline__ float4 f4_mul(float a, float4 w) {
    return make_float4(a * w.x, a * w.y, a * w.z, a * w.w);
}
__device__ __forceinline__ float4 f4_add(float4 a, float4 b) {
    return make_float4(a.x + b.x, a.y + b.y, a.z + b.z, a.w + b.w);
}
__device__ __forceinline__ float f4_dot(float4 a, float4 b) {
    return a.x * b.x + a.y * b.y + a.z * b.z + a.w * b.w;
}

// SMEM layout (floats):
//  Xs   [288*16]      = 4608   @0
//  rS   [288*32]      = 9216   @4608
//  vbuf [8*32*16]     = 4096   @13824
//  vcur [32*16]       = 512    @17920
//  invd [32]          = 32     @18432
//  mred [8*32]        = 256    @18464
//  nred [8*32]        = 256    @18720
#define SMEM_FLOATS 18976

// p_out has 4*32*16*8*8 = 131072 elements; a_out follows it.
#define AOUT_BASE 131072

// u[16] = X[B] (4x4) @ W[B,C] (4x4), C = lane. 4x LDG.128 for W.
#define COMPUTE_U(B, u0, u1, u2, u3)                                           \
    {                                                                          \
        const float4* Wp = Wt4_buf + ((B) << 7) + lane;                        \
        float4 w0 = Wp[0], w1 = Wp[32], w2 = Wp[64], w3 = Wp[96];              \
        const float4* Xp = Xv + ((B) << 2);                                    \
        float4 xr0 = Xp[0], xr1 = Xp[1], xr2 = Xp[2], xr3 = Xp[3];             \
        u0 = f4_mul(xr0.x, w0);                                                \
        u0 = f4_fma(xr0.y, w1, u0); u0 = f4_fma(xr0.z, w2, u0);                \
        u0 = f4_fma(xr0.w, w3, u0);                                            \
        u1 = f4_mul(xr1.x, w0);                                                \
        u1 = f4_fma(xr1.y, w1, u1); u1 = f4_fma(xr1.z, w2, u1);                \
        u1 = f4_fma(xr1.w, w3, u1);                                            \
        u2 = f4_mul(xr2.x, w0);                                                \
        u2 = f4_fma(xr2.y, w1, u2); u2 = f4_fma(xr2.z, w2, u2);                \
        u2 = f4_fma(xr2.w, w3, u2);                                            \
        u3 = f4_mul(xr3.x, w0);                                                \
        u3 = f4_fma(xr3.y, w1, u3); u3 = f4_fma(xr3.z, w2, u3);                \
        u3 = f4_fma(xr3.w, w3, u3);                                            \
    }

__global__ __launch_bounds__(256, 2)
void convcaps_kernel(const float* __restrict__ x,
                     float* __restrict__ out) {
    extern __shared__ float smem[];
    float* Xs   = smem;
    float* rS   = smem + 4608;
    float* vbuf = smem + 13824;
    float* vcur = smem + 17920;
    float* invd = smem + 18432;
    float* mred = smem + 18464;
    float* nred = smem + 18720;

    const int tid  = threadIdx.x;
    const int lane = tid & 31;     // = C
    const int wp   = tid >> 5;     // warp id, B ≡ wp (mod 8)
    const int pos  = blockIdx.x;   // b*64 + h*8 + w
    const int b    = pos >> 6;
    const int hw   = pos & 63;
    const int h    = hw >> 3;
    const int w    = hw & 7;

    // ---- gather patch poses X[B_=Bcap*9+ki*3+kj][ps] with zero padding ----
    for (int idx = tid; idx < 4608; idx += 256) {
        int B_ = idx >> 4, p = idx & 15;
        int Bcap = B_ / 9;
        int kk = B_ - Bcap * 9;
        int ki = kk / 3, kj = kk - ki * 3;
        int hh = 2 * h + ki - 1, ww = 2 * w + kj - 1;
        float val = 0.f;
        if ((unsigned)hh < 16u && (unsigned)ww < 16u)
            val = x[(((b * 32 + Bcap) * 16 + p) << 8) + (hh << 4) + ww];
        Xs[idx] = val;
    }
    __syncthreads();

    const float4* Xv    = reinterpret_cast<const float4*>(Xs);
    float4*       vbufv = reinterpret_cast<float4*>(vbuf);
    float4*       vcurv = reinterpret_cast<float4*>(vcur);

    float4 a0 = make_float4(0, 0, 0, 0), a1 = a0, a2 = a0, a3 = a0;

    // ================= PASS A: norms (for max-min) + uniform sum ==========
    {
        float mx = -3.4e38f, mn = 3.4e38f;
        for (int B = wp; B < 288; B += 16) {
            float4 p0, p1, p2, p3, q0, q1, q2, q3;
            COMPUTE_U(B,     p0, p1, p2, p3)
            COMPUTE_U(B + 8, q0, q1, q2, q3)
            float sa = f4_dot(p0, p0) + f4_dot(p1, p1) +
                       f4_dot(p2, p2) + f4_dot(p3, p3);
            float sb = f4_dot(q0, q0) + f4_dot(q1, q1) +
                       f4_dot(q2, q2) + f4_dot(q3, q3);
            float na = __fsqrt_rn(sa + EPSF);
            float nb = __fsqrt_rn(sb + EPSF);
            mx = fmaxf(mx, fmaxf(na, nb));
            mn = fminf(mn, fminf(na, nb));
            a0 = f4_add(a0, f4_add(p0, q0)); a1 = f4_add(a1, f4_add(p1, q1));
            a2 = f4_add(a2, f4_add(p2, q2)); a3 = f4_add(a3, f4_add(p3, q3));
        }
        mred[(wp << 5) + lane] = mx;
        nred[(wp << 5) + lane] = mn;
        int base = ((wp << 5) + lane) << 2;
        vbufv[base + 0] = a0; vbufv[base + 1] = a1;
        vbufv[base + 2] = a2; vbufv[base + 3] = a3;
    }
    __syncthreads();
    if (tid < 32) {
        float M = -3.4e38f, m = 3.4e38f;
        #pragma unroll
        for (int k = 0; k < 8; k++) {
            M = fmaxf(M, mred[(k << 5) + tid]);
            m = fminf(m, nred[(k << 5) + tid]);
        }
        invd[tid] = 1.f / (M - m);
    }
    __syncthreads();
    // reduce across warps + squash -> v0
    if (tid < 128) {
        int C = tid >> 2;
        float4 acc = vbufv[tid];
        #pragma unroll
        for (int k = 1; k < 8; k++) acc = f4_add(acc, vbufv[(k << 7) + tid]);
        float f = invd[C] * (1.f / 32.f);   // uniform c = 1/32, u = u_raw/d
        acc = f4_mul(f, acc);
        float s = f4_dot(acc, acc);
        s += __shfl_xor_sync(0xffffffffu, s, 1);
        s += __shfl_xor_sync(0xffffffffu, s, 2);
        float nrm = __fsqrt_rn(s + EPSF);
        vcurv[tid] = f4_mul(1.f / (1.f + nrm), acc);
    }
    __syncthreads();

    const float invd_c = invd[lane];

    // ================= PASS B: r1 = u.v0, c1 = softmax_C, accum c1*u ======
    {
        float4 vl0 = vcurv[(lane << 2) + 0], vl1 = vcurv[(lane << 2) + 1];
        float4 vl2 = vcurv[(lane << 2) + 2], vl3 = vcurv[(lane << 2) + 3];
        a0 = make_float4(0, 0, 0, 0); a1 = a0; a2 = a0; a3 = a0;
        for (int B = wp; B < 288; B += 16) {
            float4 p0, p1, p2, p3, q0, q1, q2, q3;
            COMPUTE_U(B,     p0, p1, p2, p3)
            COMPUTE_U(B + 8, q0, q1, q2, q3)
            float ra = (f4_dot(p0, vl0) + f4_dot(p1, vl1) +
                        f4_dot(p2, vl2) + f4_dot(p3, vl3)) * invd_c;
            float rb = (f4_dot(q0, vl0) + f4_dot(q1, vl1) +
                        f4_dot(q2, vl2) + f4_dot(q3, vl3)) * invd_c;
            rS[(B << 5) + lane]       = ra;
            rS[((B + 8) << 5) + lane] = rb;
            float ea = __expf(ra), eb = __expf(rb);
            float sa = ea, sb = eb;
            #pragma unroll
            for (int o = 16; o > 0; o >>= 1) {
                sa += __shfl_xor_sync(0xffffffffu, sa, o);
                sb += __shfl_xor_sync(0xffffffffu, sb, o);
            }
            float ca = ea * __frcp_rn(sa);
            float cb = eb * __frcp_rn(sb);
            a0 = f4_fma(ca, p0, a0); a0 = f4_fma(cb, q0, a0);
            a1 = f4_fma(ca, p1, a1); a1 = f4_fma(cb, q1, a1);
            a2 = f4_fma(ca, p2, a2); a2 = f4_fma(cb, q2, a2);
            a3 = f4_fma(ca, p3, a3); a3 = f4_fma(cb, q3, a3);
        }
        int base = ((wp << 5) + lane) << 2;
        vbufv[base + 0] = a0; vbufv[base + 1] = a1;
        vbufv[base + 2] = a2; vbufv[base + 3] = a3;
    }
    __syncthreads();
    if (tid < 128) {
        int C = tid >> 2;
        float4 acc = vbufv[tid];
        #pragma unroll
        for (int k = 1; k < 8; k++) acc = f4_add(acc, vbufv[(k << 7) + tid]);
        acc = f4_mul(invd[C], acc);
        float s = f4_dot(acc, acc);
        s += __shfl_xor_sync(0xffffffffu, s, 1);
        s += __shfl_xor_sync(0xffffffffu, s, 2);
        float nrm = __fsqrt_rn(s + EPSF);
        vcurv[tid] = f4_mul(1.f / (1.f + nrm), acc);
    }
    __syncthreads();

    // ================= PASS C: r2 = r1 + u.v1, c2, accum, output ==========
    {
        float4 vl0 = vcurv[(lane << 2) + 0], vl1 = vcurv[(lane << 2) + 1];
        float4 vl2 = vcurv[(lane << 2) + 2], vl3 = vcurv[(lane << 2) + 3];
        a0 = make_float4(0, 0, 0, 0); a1 = a0; a2 = a0; a3 = a0;
        for (int B = wp; B < 288; B += 16) {
            float4 p0, p1, p2, p3, q0, q1, q2, q3;
            COMPUTE_U(B,     p0, p1, p2, p3)
            COMPUTE_U(B + 8, q0, q1, q2, q3)
            float ra = rS[(B << 5) + lane] +
                       (f4_dot(p0, vl0) + f4_dot(p1, vl1) +
                        f4_dot(p2, vl2) + f4_dot(p3, vl3)) * invd_c;
            float rb = rS[((B + 8) << 5) + lane] +
                       (f4_dot(q0, vl0) + f4_dot(q1, vl1) +
                        f4_dot(q2, vl2) + f4_dot(q3, vl3)) * invd_c;
            float ea = __expf(ra), eb = __expf(rb);
            float sa = ea, sb = eb;
            #pragma unroll
            for (int o = 16; o > 0; o >>= 1) {
                sa += __shfl_xor_sync(0xffffffffu, sa, o);
                sb += __shfl_xor_sync(0xffffffffu, sb, o);
            }
            float ca = ea * __frcp_rn(sa);
            float cb = eb * __frcp_rn(sb);
            a0 = f4_fma(ca, p0, a0); a0 = f4_fma(cb, q0, a0);
            a1 = f4_fma(ca, p1, a1); a1 = f4_fma(cb, q1, a1);
            a2 = f4_fma(ca, p2, a2); a2 = f4_fma(cb, q2, a2);
            a3 = f4_fma(ca, p3, a3); a3 = f4_fma(cb, q3, a3);
        }
        int base = ((wp << 5) + lane) << 2;
        vbufv[base + 0] = a0; vbufv[base + 1] = a1;
        vbufv[base + 2] = a2; vbufv[base + 3] = a3;
    }
    __syncthreads();
    if (tid < 128) {
        int C = tid >> 2, q = tid & 3;
        float4 acc = vbufv[tid];
        #pragma unroll
        for (int k = 1; k < 8; k++) acc = f4_add(acc, vbufv[(k << 7) + tid]);
        acc = f4_mul(invd[C], acc);
        float s = f4_dot(acc, acc);
        s += __shfl_xor_sync(0xffffffffu, s, 1);
        s += __shfl_xor_sync(0xffffffffu, s, 2);
        float nrm = __fsqrt_rn(s + EPSF);
        acc = f4_mul(1.f / (1.f + nrm), acc);        // v2 (p_out)
        float s2 = f4_dot(acc, acc);
        s2 += __shfl_xor_sync(0xffffffffu, s2, 1);
        s2 += __shfl_xor_sync(0xffffffffu, s2, 2);
        float aout = __fsqrt_rn(s2 + EPSF);          // a_out = safe_norm(v2)
        // p_out[b, C, ps, h, w]; ps = q*4 .. q*4+3
        int basep = (((b * 32 + C) * 16 + (q << 2)) << 6) + hw;
        out[basep]       = acc.x;
        out[basep + 64]  = acc.y;
        out[basep + 128] = acc.z;
        out[basep + 192] = acc.w;
        if (q == 0)
            out[AOUT_BASE + ((b * 32 + C) << 6) + hw] = aout;
    }
}

extern "C" void kernel_launch(void* const* d_in, const int* in_sizes, int n_in,
                              void* d_out, int out_size) {
    (void)out_size;
    // Resolve inputs BY SIZE — immune to metadata ordering.
    //   x:    4*32*16*16*16 = 524288
    //   a:    4*32*16*16    =  32768 (unused by the reference computation)
    //   W_ij: 288*32*4*4    = 147456
    const float* x  = nullptr;
    const float* Wg = nullptr;
    for (int i = 0; i < n_in; i++) {
        if (in_sizes[i] == 524288)      x  = (const float*)d_in[i];
        else if (in_sizes[i] == 147456) Wg = (const float*)d_in[i];
    }
    float* out = (float*)d_out;

    transpose_W_kernel<<<(288 * 16 * 32 + 255) / 256, 256>>>(Wg);

    const size_t smem_bytes = SMEM_FLOATS * sizeof(float);
    cudaFuncSetAttribute(convcaps_kernel,
                         cudaFuncAttributeMaxDynamicSharedMemorySize,
                         (int)smem_bytes);
    convcaps_kernel<<<256, 256, smem_bytes>>>(x, out);
}

// round 8
// speedup vs baseline: 1.5464x; 1.0566x over previous
#include <cuda_runtime.h>
#include <math.h>

#define EPSF 1e-5f

// Re-laid-out weights: Wt4[B][g][C] (float4), g = jk/4.
// Wt4[(B*4+g)*32 + C] = { W[B][C][4g], ..., W[B][C][4g+3] }
__device__ float4 Wt4_buf[288 * 4 * 32];

__global__ void transpose_W_kernel(const float* __restrict__ Wg) {
    int idx = blockIdx.x * 256 + threadIdx.x;   // linear over output floats
    if (idx >= 288 * 16 * 32) return;
    int q = idx & 3;
    int C = (idx >> 2) & 31;
    int g = (idx >> 7) & 3;
    int B = idx >> 9;
    ((float*)Wt4_buf)[idx] = Wg[((B << 5) + C) * 16 + (g << 2) + q];
}

__device__ __forceinline__ float warp_sum(float v) {
    #pragma unroll
    for (int o = 16; o > 0; o >>= 1)
        v += __shfl_xor_sync(0xffffffffu, v, o);
    return v;
}

__device__ __forceinline__ float4 f4_fma(float a, float4 w, float4 acc) {
    acc.x = fmaf(a, w.x, acc.x);
    acc.y = fmaf(a, w.y, acc.y);
    acc.z = fmaf(a, w.z, acc.z);
    acc.w = fmaf(a, w.w, acc.w);
    return acc;
}
__device__ __forceinline__ float4 f4_mul(float a, float4 w) {
    return make_float4(a * w.x, a * w.y, a * w.z, a * w.w);
}
__device__ __forceinline__ float4 f4_add(float4 a, float4 b) {
    return make_float4(a.x + b.x, a.y + b.y, a.z + b.z, a.w + b.w);
}
__device__ __forceinline__ float f4_dot(float4 a, float4 b) {
    return a.x * b.x + a.y * b.y + a.z * b.z + a.w * b.w;
}

// SMEM layout (floats):
//  Xs   [288*16]      = 4608   @0
//  rS   [288*32]      = 9216   @4608
//  vbuf [8*32*16]     = 4096   @13824
//  vcur [32*16]       = 512    @17920
//  invd [32]          = 32     @18432
//  mred [8*32]        = 256    @18464
//  nred [8*32]        = 256    @18720
#define SMEM_FLOATS 18976

// p_out has 4*32*16*8*8 = 131072 elements; a_out follows it.
#define AOUT_BASE 131072

#define LOADW(B, w0, w1, w2, w3)                                               \
    {                                                                          \
        const float4* Wp_ = Wt4_buf + ((B) << 7) + lane;                       \
        w0 = Wp_[0]; w1 = Wp_[32]; w2 = Wp_[64]; w3 = Wp_[96];                 \
    }

// u[16] = X[B] (4x4) @ W (registers), C = lane.
#define COMPUTE_U_W(B, w0, w1, w2, w3, u0, u1, u2, u3)                         \
    {                                                                          \
        const float4* Xp = Xv + ((B) << 2);                                    \
        float4 xr0 = Xp[0], xr1 = Xp[1], xr2 = Xp[2], xr3 = Xp[3];             \
        u0 = f4_mul(xr0.x, w0);                                                \
        u0 = f4_fma(xr0.y, w1, u0); u0 = f4_fma(xr0.z, w2, u0);                \
        u0 = f4_fma(xr0.w, w3, u0);                                            \
        u1 = f4_mul(xr1.x, w0);                                                \
        u1 = f4_fma(xr1.y, w1, u1); u1 = f4_fma(xr1.z, w2, u1);                \
        u1 = f4_fma(xr1.w, w3, u1);                                            \
        u2 = f4_mul(xr2.x, w0);                                                \
        u2 = f4_fma(xr2.y, w1, u2); u2 = f4_fma(xr2.z, w2, u2);                \
        u2 = f4_fma(xr2.w, w3, u2);                                            \
        u3 = f4_mul(xr3.x, w0);                                                \
        u3 = f4_fma(xr3.y, w1, u3); u3 = f4_fma(xr3.z, w2, u3);                \
        u3 = f4_fma(xr3.w, w3, u3);                                            \
    }

__global__ __launch_bounds__(256, 2)
void convcaps_kernel(const float* __restrict__ x,
                     float* __restrict__ out) {
    extern __shared__ float smem[];
    float* Xs   = smem;
    float* rS   = smem + 4608;
    float* vbuf = smem + 13824;
    float* vcur = smem + 17920;
    float* invd = smem + 18432;
    float* mred = smem + 18464;
    float* nred = smem + 18720;

    const int tid  = threadIdx.x;
    const int lane = tid & 31;     // = C
    const int wp   = tid >> 5;     // warp id, B ≡ wp (mod 8)
    const int pos  = blockIdx.x;   // b*64 + h*8 + w
    const int b    = pos >> 6;
    const int hw   = pos & 63;
    const int h    = hw >> 3;
    const int w    = hw & 7;

    // ---- gather patch poses X[B_=Bcap*9+ki*3+kj][ps] with zero padding ----
    for (int idx = tid; idx < 4608; idx += 256) {
        int B_ = idx >> 4, p = idx & 15;
        int Bcap = B_ / 9;
        int kk = B_ - Bcap * 9;
        int ki = kk / 3, kj = kk - ki * 3;
        int hh = 2 * h + ki - 1, ww = 2 * w + kj - 1;
        float val = 0.f;
        if ((unsigned)hh < 16u && (unsigned)ww < 16u)
            val = x[(((b * 32 + Bcap) * 16 + p) << 8) + (hh << 4) + ww];
        Xs[idx] = val;
    }
    __syncthreads();

    const float4* Xv    = reinterpret_cast<const float4*>(Xs);
    float4*       vbufv = reinterpret_cast<float4*>(vbuf);
    float4*       vcurv = reinterpret_cast<float4*>(vcur);

    float4 a0 = make_float4(0, 0, 0, 0), a1 = a0, a2 = a0, a3 = a0;

    // ================= PASS A: norms (for max-min) + uniform sum ==========
    {
        float mx = -3.4e38f, mn = 3.4e38f;
        float4 w0, w1, w2, w3;
        LOADW(wp, w0, w1, w2, w3)
        #pragma unroll 2
        for (int k = 0; k < 36; k++) {
            int B  = wp + (k << 3);
            int Bn = (k < 35) ? B + 8 : wp;
            float4 n0, n1, n2, n3;
            LOADW(Bn, n0, n1, n2, n3)           // prefetch next iteration
            float4 u0, u1, u2, u3;
            COMPUTE_U_W(B, w0, w1, w2, w3, u0, u1, u2, u3)
            float ss = f4_dot(u0, u0) + f4_dot(u1, u1) +
                       f4_dot(u2, u2) + f4_dot(u3, u3);
            float nrm = __fsqrt_rn(ss + EPSF);
            mx = fmaxf(mx, nrm);
            mn = fminf(mn, nrm);
            a0 = f4_add(a0, u0); a1 = f4_add(a1, u1);
            a2 = f4_add(a2, u2); a3 = f4_add(a3, u3);
            w0 = n0; w1 = n1; w2 = n2; w3 = n3;
        }
        mred[(wp << 5) + lane] = mx;
        nred[(wp << 5) + lane] = mn;
        int base = ((wp << 5) + lane) << 2;
        vbufv[base + 0] = a0; vbufv[base + 1] = a1;
        vbufv[base + 2] = a2; vbufv[base + 3] = a3;
    }
    __syncthreads();
    if (tid < 32) {
        float M = -3.4e38f, m = 3.4e38f;
        #pragma unroll
        for (int k = 0; k < 8; k++) {
            M = fmaxf(M, mred[(k << 5) + tid]);
            m = fminf(m, nred[(k << 5) + tid]);
        }
        invd[tid] = 1.f / (M - m);
    }
    __syncthreads();
    // reduce across warps + squash -> v0
    if (tid < 128) {
        int C = tid >> 2;
        float4 acc = vbufv[tid];
        #pragma unroll
        for (int k = 1; k < 8; k++) acc = f4_add(acc, vbufv[(k << 7) + tid]);
        float f = invd[C] * (1.f / 32.f);   // uniform c = 1/32, u = u_raw/d
        acc = f4_mul(f, acc);
        float s = f4_dot(acc, acc);
        s += __shfl_xor_sync(0xffffffffu, s, 1);
        s += __shfl_xor_sync(0xffffffffu, s, 2);
        float nrm = __fsqrt_rn(s + EPSF);
        vcurv[tid] = f4_mul(1.f / (1.f + nrm), acc);
    }
    __syncthreads();

    const float invd_c = invd[lane];

    // ================= PASS B: r1 = u.v0, c1 = softmax_C, accum c1*u ======
    {
        float4 vl0 = vcurv[(lane << 2) + 0], vl1 = vcurv[(lane << 2) + 1];
        float4 vl2 = vcurv[(lane << 2) + 2], vl3 = vcurv[(lane << 2) + 3];
        a0 = make_float4(0, 0, 0, 0); a1 = a0; a2 = a0; a3 = a0;
        float4 w0, w1, w2, w3;
        LOADW(wp, w0, w1, w2, w3)
        #pragma unroll 2
        for (int k = 0; k < 36; k++) {
            int B  = wp + (k << 3);
            int Bn = (k < 35) ? B + 8 : wp;
            float4 n0, n1, n2, n3;
            LOADW(Bn, n0, n1, n2, n3)
            float4 u0, u1, u2, u3;
            COMPUTE_U_W(B, w0, w1, w2, w3, u0, u1, u2, u3)
            float r = (f4_dot(u0, vl0) + f4_dot(u1, vl1) +
                       f4_dot(u2, vl2) + f4_dot(u3, vl3)) * invd_c;
            rS[(B << 5) + lane] = r;
            float e = __expf(r);
            float s = warp_sum(e);
            float c = __fdividef(e, s);
            a0 = f4_fma(c, u0, a0); a1 = f4_fma(c, u1, a1);
            a2 = f4_fma(c, u2, a2); a3 = f4_fma(c, u3, a3);
            w0 = n0; w1 = n1; w2 = n2; w3 = n3;
        }
        int base = ((wp << 5) + lane) << 2;
        vbufv[base + 0] = a0; vbufv[base + 1] = a1;
        vbufv[base + 2] = a2; vbufv[base + 3] = a3;
    }
    __syncthreads();
    if (tid < 128) {
        int C = tid >> 2;
        float4 acc = vbufv[tid];
        #pragma unroll
        for (int k = 1; k < 8; k++) acc = f4_add(acc, vbufv[(k << 7) + tid]);
        acc = f4_mul(invd[C], acc);
        float s = f4_dot(acc, acc);
        s += __shfl_xor_sync(0xffffffffu, s, 1);
        s += __shfl_xor_sync(0xffffffffu, s, 2);
        float nrm = __fsqrt_rn(s + EPSF);
        vcurv[tid] = f4_mul(1.f / (1.f + nrm), acc);
    }
    __syncthreads();

    // ================= PASS C: r2 = r1 + u.v1, c2, accum, output ==========
    {
        float4 vl0 = vcurv[(lane << 2) + 0], vl1 = vcurv[(lane << 2) + 1];
        float4 vl2 = vcurv[(lane << 2) + 2], vl3 = vcurv[(lane << 2) + 3];
        a0 = make_float4(0, 0, 0, 0); a1 = a0; a2 = a0; a3 = a0;
        float4 w0, w1, w2, w3;
        LOADW(wp, w0, w1, w2, w3)
        #pragma unroll 2
        for (int k = 0; k < 36; k++) {
            int B  = wp + (k << 3);
            int Bn = (k < 35) ? B + 8 : wp;
            float4 n0, n1, n2, n3;
            LOADW(Bn, n0, n1, n2, n3)
            float4 u0, u1, u2, u3;
            COMPUTE_U_W(B, w0, w1, w2, w3, u0, u1, u2, u3)
            float r = rS[(B << 5) + lane] +
                      (f4_dot(u0, vl0) + f4_dot(u1, vl1) +
                       f4_dot(u2, vl2) + f4_dot(u3, vl3)) * invd_c;
            float e = __expf(r);
            float s = warp_sum(e);
            float c = __fdividef(e, s);
            a0 = f4_fma(c, u0, a0); a1 = f4_fma(c, u1, a1);
            a2 = f4_fma(c, u2, a2); a3 = f4_fma(c, u3, a3);
            w0 = n0; w1 = n1; w2 = n2; w3 = n3;
        }
        int base = ((wp << 5) + lane) << 2;
        vbufv[base + 0] = a0; vbufv[base + 1] = a1;
        vbufv[base + 2] = a2; vbufv[base + 3] = a3;
    }
    __syncthreads();
    if (tid < 128) {
        int C = tid >> 2, q = tid & 3;
        float4 acc = vbufv[tid];
        #pragma unroll
        for (int k = 1; k < 8; k++) acc = f4_add(acc, vbufv[(k << 7) + tid]);
        acc = f4_mul(invd[C], acc);
        float s = f4_dot(acc, acc);
        s += __shfl_xor_sync(0xffffffffu, s, 1);
        s += __shfl_xor_sync(0xffffffffu, s, 2);
        float nrm = __fsqrt_rn(s + EPSF);
        acc = f4_mul(1.f / (1.f + nrm), acc);        // v2 (p_out)
        float s2 = f4_dot(acc, acc);
        s2 += __shfl_xor_sync(0xffffffffu, s2, 1);
        s2 += __shfl_xor_sync(0xffffffffu, s2, 2);
        float aout = __fsqrt_rn(s2 + EPSF);          // a_out = safe_norm(v2)
        // p_out[b, C, ps, h, w]; ps = q*4 .. q*4+3
        int basep = (((b * 32 + C) * 16 + (q << 2)) << 6) + hw;
        out[basep]       = acc.x;
        out[basep + 64]  = acc.y;
        out[basep + 128] = acc.z;
        out[basep + 192] = acc.w;
        if (q == 0)
            out[AOUT_BASE + ((b * 32 + C) << 6) + hw] = aout;
    }
}

extern "C" void kernel_launch(void* const* d_in, const int* in_sizes, int n_in,
                              void* d_out, int out_size) {
    (void)out_size;
    // Resolve inputs BY SIZE — immune to metadata ordering.
    //   x:    4*32*16*16*16 = 524288
    //   a:    4*32*16*16    =  32768 (unused by the reference computation)
    //   W_ij: 288*32*4*4    = 147456
    const float* x  = nullptr;
    const float* Wg = nullptr;
    for (int i = 0; i < n_in; i++) {
        if (in_sizes[i] == 524288)      x  = (const float*)d_in[i];
        else if (in_sizes[i] == 147456) Wg = (const float*)d_in[i];
    }
    float* out = (float*)d_out;

    transpose_W_kernel<<<(288 * 16 * 32 + 255) / 256, 256>>>(Wg);

    const size_t smem_bytes = SMEM_FLOATS * sizeof(float);
    cudaFuncSetAttribute(convcaps_kernel,
                         cudaFuncAttributeMaxDynamicSharedMemorySize,
                         (int)smem_bytes);
    convcaps_kernel<<<256, 256, smem_bytes>>>(x, out);
}

// round 9
// speedup vs baseline: 1.6268x; 1.0520x over previous
#include <cuda_runtime.h>
#include <math.h>

#define EPSF 1e-5f

// Re-laid-out weights: Wt4[B][g][C] (float4), g = jk/4.
// Wt4[(B*4+g)*32 + C] = { W[B][C][4g], ..., W[B][C][4g+3] }
__device__ float4 Wt4_buf[288 * 4 * 32];

__global__ void transpose_W_kernel(const float* __restrict__ Wg) {
    int idx = blockIdx.x * 256 + threadIdx.x;   // linear over output floats
    if (idx >= 288 * 16 * 32) return;
    int q = idx & 3;
    int C = (idx >> 2) & 31;
    int g = (idx >> 7) & 3;
    int B = idx >> 9;
    ((float*)Wt4_buf)[idx] = Wg[((B << 5) + C) * 16 + (g << 2) + q];
}

typedef unsigned long long u64;

// packed f32x2 helpers (sm_100 PTX)
#define PACK2(d, s)      asm("mov.b64 %0, {%1, %1};" : "=l"(d) : "f"(s))
#define UNPK2(lo, hi, s) asm("mov.b64 {%0, %1}, %2;" : "=f"(lo), "=f"(hi) : "l"(s))
#define FMA2(d, a, b, c) asm("fma.rn.f32x2 %0, %1, %2, %3;" : "=l"(d) : "l"(a), "l"(b), "l"(c))
#define MUL2(d, a, b)    asm("mul.rn.f32x2 %0, %1, %2;" : "=l"(d) : "l"(a), "l"(b))
#define ADD2(d, a, b)    asm("add.rn.f32x2 %0, %1, %2;" : "=l"(d) : "l"(a), "l"(b))

__device__ __forceinline__ float warp_sum(float v) {
    #pragma unroll
    for (int o = 16; o > 0; o >>= 1)
        v += __shfl_xor_sync(0xffffffffu, v, o);
    return v;
}

// SMEM layout (floats):
//  Xs   [288*16]      = 4608   @0
//  vbuf [8*32*16]     = 4096   @4608
//  vcur [32*16]       = 512    @8704
//  invd [32]          = 32     @9216
//  mred [8*32]        = 256    @9248
//  nred [8*32]        = 256    @9504
#define SMEM_FLOATS 9760

// p_out has 4*32*16*8*8 = 131072 elements; a_out follows it.
#define AOUT_BASE 131072

#define LOADW(B, wa0, wb0, wa1, wb1, wa2, wb2, wa3, wb3)                       \
    {                                                                          \
        const ulonglong2* Wp_ =                                                \
            reinterpret_cast<const ulonglong2*>(Wt4_buf) + ((B) << 7) + lane;  \
        ulonglong2 t0 = Wp_[0], t1 = Wp_[32], t2 = Wp_[64], t3 = Wp_[96];      \
        wa0 = t0.x; wb0 = t0.y; wa1 = t1.x; wb1 = t1.y;                        \
        wa2 = t2.x; wb2 = t2.y; wa3 = t3.x; wb3 = t3.y;                        \
    }

// u[16] = X[B] (4x4) @ W (packed regs). Produces 8 packed u64 (ua_i, ub_i).
#define COMPUTE_U_P(B, wa0, wb0, wa1, wb1, wa2, wb2, wa3, wb3,                 \
                    ua0, ub0, ua1, ub1, ua2, ub2, ua3, ub3)                    \
    {                                                                          \
        const float4* Xp = Xv + ((B) << 2);                                    \
        float4 xr0 = Xp[0], xr1 = Xp[1], xr2 = Xp[2], xr3 = Xp[3];             \
        u64 xp0, xp1, xp2, xp3;                                                \
        PACK2(xp0, xr0.x); PACK2(xp1, xr0.y); PACK2(xp2, xr0.z); PACK2(xp3, xr0.w); \
        MUL2(ua0, xp0, wa0); MUL2(ub0, xp0, wb0);                              \
        FMA2(ua0, xp1, wa1, ua0); FMA2(ub0, xp1, wb1, ub0);                    \
        FMA2(ua0, xp2, wa2, ua0); FMA2(ub0, xp2, wb2, ub0);                    \
        FMA2(ua0, xp3, wa3, ua0); FMA2(ub0, xp3, wb3, ub0);                    \
        PACK2(xp0, xr1.x); PACK2(xp1, xr1.y); PACK2(xp2, xr1.z); PACK2(xp3, xr1.w); \
        MUL2(ua1, xp0, wa0); MUL2(ub1, xp0, wb0);                              \
        FMA2(ua1, xp1, wa1, ua1); FMA2(ub1, xp1, wb1, ub1);                    \
        FMA2(ua1, xp2, wa2, ua1); FMA2(ub1, xp2, wb2, ub1);                    \
        FMA2(ua1, xp3, wa3, ua1); FMA2(ub1, xp3, wb3, ub1);                    \
        PACK2(xp0, xr2.x); PACK2(xp1, xr2.y); PACK2(xp2, xr2.z); PACK2(xp3, xr2.w); \
        MUL2(ua2, xp0, wa0); MUL2(ub2, xp0, wb0);                              \
        FMA2(ua2, xp1, wa1, ua2); FMA2(ub2, xp1, wb1, ub2);                    \
        FMA2(ua2, xp2, wa2, ua2); FMA2(ub2, xp2, wb2, ub2);                    \
        FMA2(ua2, xp3, wa3, ua2); FMA2(ub2, xp3, wb3, ub2);                    \
        PACK2(xp0, xr3.x); PACK2(xp1, xr3.y); PACK2(xp2, xr3.z); PACK2(xp3, xr3.w); \
        MUL2(ua3, xp0, wa0); MUL2(ub3, xp0, wb0);                              \
        FMA2(ua3, xp1, wa1, ua3); FMA2(ub3, xp1, wb1, ub3);                    \
        FMA2(ua3, xp2, wa2, ua3); FMA2(ub3, xp2, wb2, ub3);                    \
        FMA2(ua3, xp3, wa3, ua3); FMA2(ub3, xp3, wb3, ub3);                    \
    }

// packed elementwise dot of 8 pairs -> scalar (lo+hi)
#define PDOT8(res, ua0, ub0, ua1, ub1, ua2, ub2, ua3, ub3,                     \
              va0, vb0, va1, vb1, va2, vb2, va3, vb3)                          \
    {                                                                          \
        u64 t_;                                                                \
        MUL2(t_, ua0, va0); FMA2(t_, ub0, vb0, t_);                            \
        FMA2(t_, ua1, va1, t_); FMA2(t_, ub1, vb1, t_);                        \
        FMA2(t_, ua2, va2, t_); FMA2(t_, ub2, vb2, t_);                        \
        FMA2(t_, ua3, va3, t_); FMA2(t_, ub3, vb3, t_);                        \
        float lo_, hi_;                                                        \
        UNPK2(lo_, hi_, t_);                                                   \
        res = lo_ + hi_;                                                       \
    }

__global__ __launch_bounds__(256, 2)
void convcaps_kernel(const float* __restrict__ x,
                     float* __restrict__ out) {
    extern __shared__ float smem[];
    float* Xs   = smem;
    float* vbuf = smem + 4608;
    float* vcur = smem + 8704;
    float* invd = smem + 9216;
    float* mred = smem + 9248;
    float* nred = smem + 9504;

    const int tid  = threadIdx.x;
    const int lane = tid & 31;     // = C
    const int wp   = tid >> 5;     // warp id, B ≡ wp (mod 8)
    const int pos  = blockIdx.x;   // b*64 + h*8 + w
    const int b    = pos >> 6;
    const int hw   = pos & 63;
    const int h    = hw >> 3;
    const int w    = hw & 7;

    // ---- gather patch poses X[B_=Bcap*9+ki*3+kj][ps] with zero padding ----
    for (int idx = tid; idx < 4608; idx += 256) {
        int B_ = idx >> 4, p = idx & 15;
        int Bcap = B_ / 9;
        int kk = B_ - Bcap * 9;
        int ki = kk / 3, kj = kk - ki * 3;
        int hh = 2 * h + ki - 1, ww = 2 * w + kj - 1;
        float val = 0.f;
        if ((unsigned)hh < 16u && (unsigned)ww < 16u)
            val = x[(((b * 32 + Bcap) * 16 + p) << 8) + (hh << 4) + ww];
        Xs[idx] = val;
    }
    __syncthreads();

    const float4* Xv     = reinterpret_cast<const float4*>(Xs);
    float4*       vbufv  = reinterpret_cast<float4*>(vbuf);
    float4*       vcurv  = reinterpret_cast<float4*>(vcur);
    ulonglong2*   vbufp  = reinterpret_cast<ulonglong2*>(vbuf);
    const ulonglong2* vcurp = reinterpret_cast<const ulonglong2*>(vcur);

    u64 aa0, ab0, aa1, ab1, aa2, ab2, aa3, ab3;

    // ================= PASS A: norms (for max-min) + uniform sum ==========
    {
        float mx = -3.4e38f, mn = 3.4e38f;
        u64 z = 0;
        aa0 = ab0 = aa1 = ab1 = aa2 = ab2 = aa3 = ab3 = z;
        u64 wa0, wb0, wa1, wb1, wa2, wb2, wa3, wb3;
        LOADW(wp, wa0, wb0, wa1, wb1, wa2, wb2, wa3, wb3)
        #pragma unroll 2
        for (int k = 0; k < 36; k++) {
            int B  = wp + (k << 3);
            int Bn = (k < 35) ? B + 8 : wp;
            u64 na0, nb0, na1, nb1, na2, nb2, na3, nb3;
            LOADW(Bn, na0, nb0, na1, nb1, na2, nb2, na3, nb3)   // prefetch
            u64 ua0, ub0, ua1, ub1, ua2, ub2, ua3, ub3;
            COMPUTE_U_P(B, wa0, wb0, wa1, wb1, wa2, wb2, wa3, wb3,
                           ua0, ub0, ua1, ub1, ua2, ub2, ua3, ub3)
            float ss;
            PDOT8(ss, ua0, ub0, ua1, ub1, ua2, ub2, ua3, ub3,
                      ua0, ub0, ua1, ub1, ua2, ub2, ua3, ub3)
            float nrm = __fsqrt_rn(ss + EPSF);
            mx = fmaxf(mx, nrm);
            mn = fminf(mn, nrm);
            ADD2(aa0, aa0, ua0); ADD2(ab0, ab0, ub0);
            ADD2(aa1, aa1, ua1); ADD2(ab1, ab1, ub1);
            ADD2(aa2, aa2, ua2); ADD2(ab2, ab2, ub2);
            ADD2(aa3, aa3, ua3); ADD2(ab3, ab3, ub3);
            wa0 = na0; wb0 = nb0; wa1 = na1; wb1 = nb1;
            wa2 = na2; wb2 = nb2; wa3 = na3; wb3 = nb3;
        }
        mred[(wp << 5) + lane] = mx;
        nred[(wp << 5) + lane] = mn;
        int base = ((wp << 5) + lane) << 2;
        ulonglong2 s0; s0.x = aa0; s0.y = ab0; vbufp[base + 0] = s0;
        ulonglong2 s1; s1.x = aa1; s1.y = ab1; vbufp[base + 1] = s1;
        ulonglong2 s2; s2.x = aa2; s2.y = ab2; vbufp[base + 2] = s2;
        ulonglong2 s3; s3.x = aa3; s3.y = ab3; vbufp[base + 3] = s3;
    }
    __syncthreads();
    if (tid < 32) {
        float M = -3.4e38f, m = 3.4e38f;
        #pragma unroll
        for (int k = 0; k < 8; k++) {
            M = fmaxf(M, mred[(k << 5) + tid]);
            m = fminf(m, nred[(k << 5) + tid]);
        }
        invd[tid] = 1.f / (M - m);
    }
    __syncthreads();
    // reduce across warps + squash -> v0
    if (tid < 128) {
        int C = tid >> 2;
        float4 acc = vbufv[tid];
        #pragma unroll
        for (int k = 1; k < 8; k++) {
            float4 t = vbufv[(k << 7) + tid];
            acc.x += t.x; acc.y += t.y; acc.z += t.z; acc.w += t.w;
        }
        float f = invd[C] * (1.f / 32.f);   // uniform c = 1/32, u = u_raw/d
        acc.x *= f; acc.y *= f; acc.z *= f; acc.w *= f;
        float s = acc.x * acc.x + acc.y * acc.y + acc.z * acc.z + acc.w * acc.w;
        s += __shfl_xor_sync(0xffffffffu, s, 1);
        s += __shfl_xor_sync(0xffffffffu, s, 2);
        float nrm = __fsqrt_rn(s + EPSF);
        float g = 1.f / (1.f + nrm);
        acc.x *= g; acc.y *= g; acc.z *= g; acc.w *= g;
        vcurv[tid] = acc;
    }
    __syncthreads();

    const float invd_c = invd[lane];

    // v0 packed, kept in registers for pass C (vl_C = v0 + v1)
    u64 va0, vb0, va1, vb1, va2, vb2, va3, vb3;
    {
        ulonglong2 t0 = vcurp[(lane << 2) + 0];
        ulonglong2 t1 = vcurp[(lane << 2) + 1];
        ulonglong2 t2 = vcurp[(lane << 2) + 2];
        ulonglong2 t3 = vcurp[(lane << 2) + 3];
        va0 = t0.x; vb0 = t0.y; va1 = t1.x; vb1 = t1.y;
        va2 = t2.x; vb2 = t2.y; va3 = t3.x; vb3 = t3.y;
    }

    // ================= PASS B: r1 = u.v0, c1 = softmax_C, accum c1*u ======
    {
        u64 z = 0;
        aa0 = ab0 = aa1 = ab1 = aa2 = ab2 = aa3 = ab3 = z;
        u64 wa0, wb0, wa1, wb1, wa2, wb2, wa3, wb3;
        LOADW(wp, wa0, wb0, wa1, wb1, wa2, wb2, wa3, wb3)
        #pragma unroll 2
        for (int k = 0; k < 36; k++) {
            int B  = wp + (k << 3);
            int Bn = (k < 35) ? B + 8 : wp;
            u64 na0, nb0, na1, nb1, na2, nb2, na3, nb3;
            LOADW(Bn, na0, nb0, na1, nb1, na2, nb2, na3, nb3)
            u64 ua0, ub0, ua1, ub1, ua2, ub2, ua3, ub3;
            COMPUTE_U_P(B, wa0, wb0, wa1, wb1, wa2, wb2, wa3, wb3,
                           ua0, ub0, ua1, ub1, ua2, ub2, ua3, ub3)
            float dt;
            PDOT8(dt, ua0, ub0, ua1, ub1, ua2, ub2, ua3, ub3,
                      va0, vb0, va1, vb1, va2, vb2, va3, vb3)
            float r = dt * invd_c;
            float e = __expf(r);
            float s = warp_sum(e);
            float c = __fdividef(e, s);
            u64 cP; PACK2(cP, c);
            FMA2(aa0, cP, ua0, aa0); FMA2(ab0, cP, ub0, ab0);
            FMA2(aa1, cP, ua1, aa1); FMA2(ab1, cP, ub1, ab1);
            FMA2(aa2, cP, ua2, aa2); FMA2(ab2, cP, ub2, ab2);
            FMA2(aa3, cP, ua3, aa3); FMA2(ab3, cP, ub3, ab3);
            wa0 = na0; wb0 = nb0; wa1 = na1; wb1 = nb1;
            wa2 = na2; wb2 = nb2; wa3 = na3; wb3 = nb3;
        }
        int base = ((wp << 5) + lane) << 2;
        ulonglong2 s0; s0.x = aa0; s0.y = ab0; vbufp[base + 0] = s0;
        ulonglong2 s1; s1.x = aa1; s1.y = ab1; vbufp[base + 1] = s1;
        ulonglong2 s2; s2.x = aa2; s2.y = ab2; vbufp[base + 2] = s2;
        ulonglong2 s3; s3.x = aa3; s3.y = ab3; vbufp[base + 3] = s3;
    }
    __syncthreads();
    if (tid < 128) {
        int C = tid >> 2;
        float4 acc = vbufv[tid];
        #pragma unroll
        for (int k = 1; k < 8; k++) {
            float4 t = vbufv[(k << 7) + tid];
            acc.x += t.x; acc.y += t.y; acc.z += t.z; acc.w += t.w;
        }
        float f = invd[C];
        acc.x *= f; acc.y *= f; acc.z *= f; acc.w *= f;
        float s = acc.x * acc.x + acc.y * acc.y + acc.z * acc.z + acc.w * acc.w;
        s += __shfl_xor_sync(0xffffffffu, s, 1);
        s += __shfl_xor_sync(0xffffffffu, s, 2);
        float nrm = __fsqrt_rn(s + EPSF);
        float g = 1.f / (1.f + nrm);
        acc.x *= g; acc.y *= g; acc.z *= g; acc.w *= g;
        vcurv[tid] = acc;   // v1
    }
    __syncthreads();

    // vl = v0 + v1 (linearity: r2 = r1 + u.v1*invd = invd * u.(v0+v1))
    {
        ulonglong2 t0 = vcurp[(lane << 2) + 0];
        ulonglong2 t1 = vcurp[(lane << 2) + 1];
        ulonglong2 t2 = vcurp[(lane << 2) + 2];
        ulonglong2 t3 = vcurp[(lane << 2) + 3];
        ADD2(va0, va0, t0.x); ADD2(vb0, vb0, t0.y);
        ADD2(va1, va1, t1.x); ADD2(vb1, vb1, t1.y);
        ADD2(va2, va2, t2.x); ADD2(vb2, vb2, t2.y);
        ADD2(va3, va3, t3.x); ADD2(vb3, vb3, t3.y);
    }

    // ================= PASS C: r2 = invd*u.(v0+v1), c2, accum, output ======
    {
        u64 z = 0;
        aa0 = ab0 = aa1 = ab1 = aa2 = ab2 = aa3 = ab3 = z;
        u64 wa0, wb0, wa1, wb1, wa2, wb2, wa3, wb3;
        LOADW(wp, wa0, wb0, wa1, wb1, wa2, wb2, wa3, wb3)
        #pragma unroll 2
        for (int k = 0; k < 36; k++) {
            int B  = wp + (k << 3);
            int Bn = (k < 35) ? B + 8 : wp;
            u64 na0, nb0, na1, nb1, na2, nb2, na3, nb3;
            LOADW(Bn, na0, nb0, na1, nb1, na2, nb2, na3, nb3)
            u64 ua0, ub0, ua1, ub1, ua2, ub2, ua3, ub3;
            COMPUTE_U_P(B, wa0, wb0, wa1, wb1, wa2, wb2, wa3, wb3,
                           ua0, ub0, ua1, ub1, ua2, ub2, ua3, ub3)
            float dt;
            PDOT8(dt, ua0, ub0, ua1, ub1, ua2, ub2, ua3, ub3,
                      va0, vb0, va1, vb1, va2, vb2, va3, vb3)
            float r = dt * invd_c;
            float e = __expf(r);
            float s = warp_sum(e);
            float c = __fdividef(e, s);
            u64 cP; PACK2(cP, c);
            FMA2(aa0, cP, ua0, aa0); FMA2(ab0, cP, ub0, ab0);
            FMA2(aa1, cP, ua1, aa1); FMA2(ab1, cP, ub1, ab1);
            FMA2(aa2, cP, ua2, aa2); FMA2(ab2, cP, ub2, ab2);
            FMA2(aa3, cP, ua3, aa3); FMA2(ab3, cP, ub3, ab3);
            wa0 = na0; wb0 = nb0; wa1 = na1; wb1 = nb1;
            wa2 = na2; wb2 = nb2; wa3 = na3; wb3 = nb3;
        }
        int base = ((wp << 5) + lane) << 2;
        ulonglong2 s0; s0.x = aa0; s0.y = ab0; vbufp[base + 0] = s0;
        ulonglong2 s1; s1.x = aa1; s1.y = ab1; vbufp[base + 1] = s1;
        ulonglong2 s2; s2.x = aa2; s2.y = ab2; vbufp[base + 2] = s2;
        ulonglong2 s3; s3.x = aa3; s3.y = ab3; vbufp[base + 3] = s3;
    }
    __syncthreads();
    if (tid < 128) {
        int C = tid >> 2, q = tid & 3;
        float4 acc = vbufv[tid];
        #pragma unroll
        for (int k = 1; k < 8; k++) {
            float4 t = vbufv[(k << 7) + tid];
            acc.x += t.x; acc.y += t.y; acc.z += t.z; acc.w += t.w;
        }
        float f = invd[C];
        acc.x *= f; acc.y *= f; acc.z *= f; acc.w *= f;
        float s = acc.x * acc.x + acc.y * acc.y + acc.z * acc.z + acc.w * acc.w;
        s += __shfl_xor_sync(0xffffffffu, s, 1);
        s += __shfl_xor_sync(0xffffffffu, s, 2);
        float nrm = __fsqrt_rn(s + EPSF);
        float g = 1.f / (1.f + nrm);
        acc.x *= g; acc.y *= g; acc.z *= g; acc.w *= g;   // v2 (p_out)
        float s2 = acc.x * acc.x + acc.y * acc.y + acc.z * acc.z + acc.w * acc.w;
        s2 += __shfl_xor_sync(0xffffffffu, s2, 1);
        s2 += __shfl_xor_sync(0xffffffffu, s2, 2);
        float aout = __fsqrt_rn(s2 + EPSF);               // a_out = safe_norm(v2)
        // p_out[b, C, ps, h, w]; ps = q*4 .. q*4+3
        int basep = (((b * 32 + C) * 16 + (q << 2)) << 6) + hw;
        out[basep]       = acc.x;
        out[basep + 64]  = acc.y;
        out[basep + 128] = acc.z;
        out[basep + 192] = acc.w;
        if (q == 0)
            out[AOUT_BASE + ((b * 32 + C) << 6) + hw] = aout;
    }
}

extern "C" void kernel_launch(void* const* d_in, const int* in_sizes, int n_in,
                              void* d_out, int out_size) {
    (void)out_size;
    // Resolve inputs BY SIZE — immune to metadata ordering.
    //   x:    4*32*16*16*16 = 524288
    //   a:    4*32*16*16    =  32768 (unused by the reference computation)
    //   W_ij: 288*32*4*4    = 147456
    const float* x  = nullptr;
    const float* Wg = nullptr;
    for (int i = 0; i < n_in; i++) {
        if (in_sizes[i] == 524288)      x  = (const float*)d_in[i];
        else if (in_sizes[i] == 147456) Wg = (const float*)d_in[i];
    }
    float* out = (float*)d_out;

    transpose_W_kernel<<<(288 * 16 * 32 + 255) / 256, 256>>>(Wg);

    const size_t smem_bytes = SMEM_FLOATS * sizeof(float);
    cudaFuncSetAttribute(convcaps_kernel,
                         cudaFuncAttributeMaxDynamicSharedMemorySize,
                         (int)smem_bytes);
    convcaps_kernel<<<256, 256, smem_bytes>>>(x, out);
}